// round 1
// baseline (speedup 1.0000x reference)
#include <cuda_runtime.h>
#include <cstdint>

#define NB   16384
#define NPG  9
#define RK   512
#define EPG  12
#define NN   (NB*NPG)

// ---------------- scratch (static device globals; no runtime allocation) ----
__device__ float g_m[(size_t)NN*RK];      // aggregated input to GEMM
__device__ float g_h[(size_t)NN*RK];      // GEMM output (pre-bias, pre-LN)
__device__ float g_Wt[3*RK*RK];           // tf32-rounded weights
__device__ int   g_src64;
__device__ int   g_feat64;

// ---------------- helpers ---------------------------------------------------
__device__ __forceinline__ float tf32r(float x){
    unsigned u; asm("cvt.rna.tf32.f32 %0, %1;" : "=r"(u) : "f"(x));
    return __uint_as_float(u);
}
__device__ __forceinline__ float wredsum(float v){
    #pragma unroll
    for (int o = 16; o; o >>= 1) v += __shfl_xor_sync(0xffffffffu, v, o);
    return v;
}
__device__ __forceinline__ void cp_async16(void* smem, const void* g){
    unsigned s = (unsigned)__cvta_generic_to_shared(smem);
    asm volatile("cp.async.cg.shared.global [%0], [%1], 16;\n" :: "r"(s), "l"(g));
}
__device__ __forceinline__ void cp_commit(){ asm volatile("cp.async.commit_group;\n"); }
template<int W> __device__ __forceinline__ void cp_wait(){
    asm volatile("cp.async.wait_group %0;\n" :: "n"(W));
}
__device__ __forceinline__ void mma_tf32(float* c, const unsigned* a, const unsigned* b){
    asm volatile(
        "mma.sync.aligned.m16n8k8.row.col.f32.tf32.tf32.f32 "
        "{%0,%1,%2,%3},{%4,%5,%6,%7},{%8,%9},{%0,%1,%2,%3};\n"
        : "+f"(c[0]), "+f"(c[1]), "+f"(c[2]), "+f"(c[3])
        : "r"(a[0]), "r"(a[1]), "r"(a[2]), "r"(a[3]), "r"(b[0]), "r"(b[1]));
}
__device__ __forceinline__ int read_idx(const void* p, int is64, long long i){
    return is64 ? (int)((const long long*)p)[i] : ((const int*)p)[i];
}

// ---------------- dtype detection (int32 vs int64 indices) -------------------
__global__ void detect_kernel(const int* sw, const int* fw){
    if (blockIdx.x == 0 && threadIdx.x == 0){
        int s64 = 1, f64 = 1;
        for (int i = 0; i < 32; i++){
            if (sw[2*i+1] != 0) s64 = 0;
            if (fw[2*i+1] != 0) f64 = 0;
        }
        g_src64 = s64; g_feat64 = f64;
    }
}

// ---------------- pre-round W to tf32 ---------------------------------------
__global__ void round_w_kernel(const float* __restrict__ Ws){
    int idx = blockIdx.x*blockDim.x + threadIdx.x;
    g_Wt[idx] = tf32r(Ws[idx]);
}

// ---------------- layer-0 aggregation: emb gather + norm + scatter-add ------
__global__ __launch_bounds__(256) void agg0_kernel(
    const void* __restrict__ featp, const void* __restrict__ srcp,
    const void* __restrict__ dstp, const float* __restrict__ emb)
{
    __shared__ float hs[NPG][RK];
    __shared__ float ms[NPG][RK];
    __shared__ int sl[EPG], dl[EPG], odeg[NPG], ideg[NPG], feats[NPG];
    __shared__ float onrm[NPG], inrm[NPG];
    const int g = blockIdx.x, tid = threadIdx.x;
    const int f64 = g_feat64, s64 = g_src64;

    if (tid < NPG){
        odeg[tid] = 0; ideg[tid] = 0;
        feats[tid] = read_idx(featp, f64, (long long)g*NPG + tid);
    }
    __syncthreads();
    if (tid < EPG){
        long long e = (long long)g*EPG + tid;
        int s = read_idx(srcp, s64, e) - g*NPG;
        int d = read_idx(dstp, s64, e) - g*NPG;
        sl[tid] = s; dl[tid] = d;
        atomicAdd(&odeg[s], 1); atomicAdd(&ideg[d], 1);
    }
    for (int idx = tid; idx < NPG*(RK/4); idx += 256){
        int i = idx/(RK/4), c4 = idx%(RK/4);
        float4 v = ((const float4*)(emb + (size_t)feats[i]*RK))[c4];
        ((float4*)&hs[i][0])[c4] = v;
        ((float4*)&ms[i][0])[c4] = make_float4(0.f,0.f,0.f,0.f);
    }
    __syncthreads();
    if (tid < NPG){
        onrm[tid] = odeg[tid] ? rsqrtf((float)odeg[tid]) : 1.0f;
        inrm[tid] = ideg[tid] ? rsqrtf((float)ideg[tid]) : 1.0f;
    }
    __syncthreads();
    const int f0 = tid, f1 = tid + 256;
    #pragma unroll
    for (int e = 0; e < EPG; e++){
        int s = sl[e], d = dl[e];
        float w = onrm[s];
        ms[d][f0] += hs[s][f0]*w;
        ms[d][f1] += hs[s][f1]*w;
    }
    __syncthreads();
    float* Mg = g_m + (size_t)g*NPG*RK;
    for (int idx = tid; idx < NPG*(RK/4); idx += 256){
        int i = idx/(RK/4), c4 = idx%(RK/4);
        float w = inrm[i];
        float4 v = ((float4*)&ms[i][0])[c4];
        v.x = tf32r(v.x*w); v.y = tf32r(v.y*w); v.z = tf32r(v.z*w); v.w = tf32r(v.w*w);
        ((float4*)Mg)[idx] = v;
    }
}

// -------- fused bias + LN + ReLU (prev layer) + aggregation (this layer) ----
__global__ __launch_bounds__(256) void aggln_kernel(
    const void* __restrict__ srcp, const void* __restrict__ dstp,
    const float* __restrict__ bias, const float* __restrict__ gamma,
    const float* __restrict__ beta)
{
    __shared__ float hs[NPG][RK];
    __shared__ float ms[NPG][RK];
    __shared__ float gsm[RK], btsm[RK];
    __shared__ int sl[EPG], dl[EPG], odeg[NPG], ideg[NPG];
    __shared__ float onrm[NPG], inrm[NPG], mu9[NPG], rs9[NPG];
    const int g = blockIdx.x, tid = threadIdx.x;
    const int s64 = g_src64;

    if (tid < NPG){ odeg[tid] = 0; ideg[tid] = 0; }
    for (int f = tid; f < RK; f += 256){ gsm[f] = gamma[f]; btsm[f] = beta[f]; }
    __syncthreads();
    if (tid < EPG){
        long long e = (long long)g*EPG + tid;
        int s = read_idx(srcp, s64, e) - g*NPG;
        int d = read_idx(dstp, s64, e) - g*NPG;
        sl[tid] = s; dl[tid] = d;
        atomicAdd(&odeg[s], 1); atomicAdd(&ideg[d], 1);
    }
    const float* Hg = g_h + (size_t)g*NPG*RK;
    for (int idx = tid; idx < NPG*(RK/4); idx += 256){
        int i = idx/(RK/4), c4 = idx%(RK/4);
        float4 v = ((const float4*)Hg)[idx];
        float4 b = ((const float4*)bias)[c4];
        v.x += b.x; v.y += b.y; v.z += b.z; v.w += b.w;
        ((float4*)&hs[i][0])[c4] = v;
    }
    __syncthreads();
    if (tid < NPG){
        onrm[tid] = odeg[tid] ? rsqrtf((float)odeg[tid]) : 1.0f;
        inrm[tid] = ideg[tid] ? rsqrtf((float)ideg[tid]) : 1.0f;
    }
    const int w = tid >> 5, ln = tid & 31;
    for (int r = w; r < NPG; r += 8){
        float s = 0.f, ss = 0.f;
        #pragma unroll
        for (int j = 0; j < RK/32; j++){ float v = hs[r][ln + j*32]; s += v; ss += v*v; }
        s = wredsum(s); ss = wredsum(ss);
        if (ln == 0){
            float mu = s*(1.0f/RK);
            mu9[r] = mu;
            rs9[r] = rsqrtf(ss*(1.0f/RK) - mu*mu + 1e-5f);
        }
    }
    __syncthreads();
    for (int idx = tid; idx < NPG*RK; idx += 256){
        int i = idx >> 9, f = idx & (RK-1);
        float v = (hs[i][f] - mu9[i])*rs9[i]*gsm[f] + btsm[f];
        hs[i][f] = fmaxf(v, 0.f)*onrm[i];
        ms[i][f] = 0.f;
    }
    __syncthreads();
    const int f0 = tid, f1 = tid + 256;
    #pragma unroll
    for (int e = 0; e < EPG; e++){
        int s = sl[e], d = dl[e];
        ms[d][f0] += hs[s][f0];
        ms[d][f1] += hs[s][f1];
    }
    __syncthreads();
    float* Mg = g_m + (size_t)g*NPG*RK;
    for (int idx = tid; idx < NPG*(RK/4); idx += 256){
        int i = idx/(RK/4), c4 = idx%(RK/4);
        float wn = inrm[i];
        float4 v = ((float4*)&ms[i][0])[c4];
        v.x = tf32r(v.x*wn); v.y = tf32r(v.y*wn); v.z = tf32r(v.z*wn); v.w = tf32r(v.w*wn);
        ((float4*)Mg)[idx] = v;
    }
}

// ---------------- TF32 GEMM: g_h = g_m @ Wt[layer]  (no bias, no LN) --------
#define BM 128
#define BN 128
#define BK 32
#define AS_LD (BK+8)
#define BS_LD (BN+8)
#define SMEM_GEMM ((2*BM*AS_LD + 2*BK*BS_LD)*4)

__global__ __launch_bounds__(256,2) void gemm_tf32_kernel(int layer){
    extern __shared__ float smbuf[];
    float* As = smbuf;                   // [2][BM][AS_LD]
    float* Bs = smbuf + 2*BM*AS_LD;      // [2][BK][BS_LD]
    const float* __restrict__ A = g_m;
    const float* __restrict__ W = g_Wt + (size_t)layer*RK*RK;
    float* __restrict__ C = g_h;

    const int tid = threadIdx.x;
    const int bn = blockIdx.x, bm = blockIdx.y;
    const int lane = tid & 31, warp = tid >> 5;
    const int wm = warp & 1, wn = warp >> 1;      // 2 x 4 warp grid
    const int gid = lane >> 2, tig = lane & 3;

    float c[4][4][4];
    #pragma unroll
    for (int mt = 0; mt < 4; mt++)
        #pragma unroll
        for (int nf = 0; nf < 4; nf++)
            #pragma unroll
            for (int q = 0; q < 4; q++) c[mt][nf][q] = 0.f;

    const float* Ag = A + (size_t)bm*BM*RK;
    const float* Bg = W + bn*BN;

    auto stageA = [&](int st, int k0){
        #pragma unroll
        for (int i = 0; i < 4; i++){
            int idx = tid + i*256; int r = idx >> 3, cc = idx & 7;
            cp_async16(&As[st*BM*AS_LD + r*AS_LD + cc*4], Ag + (size_t)r*RK + k0 + cc*4);
        }
    };
    auto stageB = [&](int st, int k0){
        #pragma unroll
        for (int i = 0; i < 4; i++){
            int idx = tid + i*256; int r = idx >> 5, cc = idx & 31;
            cp_async16(&Bs[st*BK*BS_LD + r*BS_LD + cc*4], Bg + (size_t)(k0 + r)*RK + cc*4);
        }
    };

    stageA(0, 0); stageB(0, 0); cp_commit();
    #pragma unroll 1
    for (int kt = 0; kt < RK/BK; kt++){
        const int cur = kt & 1;
        if (kt < RK/BK - 1){
            stageA(cur^1, (kt+1)*BK); stageB(cur^1, (kt+1)*BK); cp_commit();
            cp_wait<1>();
        } else {
            cp_wait<0>();
        }
        __syncthreads();
        const float* Ac = As + cur*BM*AS_LD;
        const float* Bc = Bs + cur*BK*BS_LD;
        #pragma unroll
        for (int ks = 0; ks < BK/8; ks++){
            const int kk = ks*8;
            unsigned a[4][4], b[4][2];
            #pragma unroll
            for (int mt = 0; mt < 4; mt++){
                int r = wm*64 + mt*16 + gid;
                a[mt][0] = __float_as_uint(Ac[ r   *AS_LD + kk + tig    ]);
                a[mt][1] = __float_as_uint(Ac[(r+8)*AS_LD + kk + tig    ]);
                a[mt][2] = __float_as_uint(Ac[ r   *AS_LD + kk + tig + 4]);
                a[mt][3] = __float_as_uint(Ac[(r+8)*AS_LD + kk + tig + 4]);
            }
            #pragma unroll
            for (int nf = 0; nf < 4; nf++){
                int cn = wn*32 + nf*8 + gid;
                b[nf][0] = __float_as_uint(Bc[(kk + tig    )*BS_LD + cn]);
                b[nf][1] = __float_as_uint(Bc[(kk + tig + 4)*BS_LD + cn]);
            }
            #pragma unroll
            for (int mt = 0; mt < 4; mt++)
                #pragma unroll
                for (int nf = 0; nf < 4; nf++)
                    mma_tf32(c[mt][nf], a[mt], b[nf]);
        }
        __syncthreads();
    }
    #pragma unroll
    for (int mt = 0; mt < 4; mt++){
        int r = bm*BM + wm*64 + mt*16 + gid;
        #pragma unroll
        for (int nf = 0; nf < 4; nf++){
            int cn = bn*BN + wn*32 + nf*8 + tig*2;
            *(float2*)&C[(size_t)r*RK + cn]     = make_float2(c[mt][nf][0], c[mt][nf][1]);
            *(float2*)&C[(size_t)(r+8)*RK + cn] = make_float2(c[mt][nf][2], c[mt][nf][3]);
        }
    }
}

// ---------------- output head: bias + LN + ReLU on first node, dot w_out ----
__global__ __launch_bounds__(256) void out_kernel(
    const float* __restrict__ bias, const float* __restrict__ gamma,
    const float* __restrict__ beta, const float* __restrict__ wout,
    const float* __restrict__ bout, float* __restrict__ out)
{
    const int g = blockIdx.x*8 + (threadIdx.x >> 5);
    const int ln = threadIdx.x & 31;
    const float* row = g_h + (size_t)g*NPG*RK;   // first node of graph g
    float v[16]; float s = 0.f, ss = 0.f;
    #pragma unroll
    for (int j = 0; j < 16; j++){
        int f = ln + j*32;
        float x = row[f] + bias[f];
        v[j] = x; s += x; ss += x*x;
    }
    s = wredsum(s); ss = wredsum(ss);
    float mu = s*(1.0f/RK);
    float rs = rsqrtf(ss*(1.0f/RK) - mu*mu + 1e-5f);
    float dot = 0.f;
    #pragma unroll
    for (int j = 0; j < 16; j++){
        int f = ln + j*32;
        float y = fmaxf((v[j]-mu)*rs*gamma[f] + beta[f], 0.f);
        dot += y*wout[f];
    }
    dot = wredsum(dot);
    if (ln == 0) out[g] = dot + bout[0];
}

// ---------------- launcher ---------------------------------------------------
extern "C" void kernel_launch(void* const* d_in, const int* in_sizes, int n_in,
                              void* d_out, int out_size){
    (void)in_sizes; (void)n_in; (void)out_size;
    const void*  feat = d_in[0];
    const void*  src  = d_in[1];
    const void*  dst  = d_in[2];
    const float* emb  = (const float*)d_in[3];
    const float* Ws   = (const float*)d_in[4];
    const float* bs   = (const float*)d_in[5];
    const float* gam  = (const float*)d_in[6];
    const float* bet  = (const float*)d_in[7];
    const float* wout = (const float*)d_in[8];
    const float* bout = (const float*)d_in[9];
    float* out = (float*)d_out;

    cudaFuncSetAttribute(gemm_tf32_kernel,
                         cudaFuncAttributeMaxDynamicSharedMemorySize, SMEM_GEMM);

    detect_kernel<<<1, 32>>>((const int*)src, (const int*)feat);
    round_w_kernel<<<3*RK*RK/256, 256>>>(Ws);

    agg0_kernel<<<NB, 256>>>(feat, src, dst, emb);
    dim3 gg(RK/BN, NN/BM);
    gemm_tf32_kernel<<<gg, 256, SMEM_GEMM>>>(0);
    aggln_kernel<<<NB, 256>>>(src, dst, bs,        gam,        bet);
    gemm_tf32_kernel<<<gg, 256, SMEM_GEMM>>>(1);
    aggln_kernel<<<NB, 256>>>(src, dst, bs + RK,   gam + RK,   bet + RK);
    gemm_tf32_kernel<<<gg, 256, SMEM_GEMM>>>(2);
    out_kernel<<<NB/8, 256>>>(bs + 2*RK, gam + 2*RK, bet + 2*RK, wout, bout, out);
}

// round 3
// speedup vs baseline: 1.3072x; 1.3072x over previous
#include <cuda_runtime.h>
#include <cstdint>

#define NB   16384
#define NPG  9
#define RK   512
#define EPG  12
#define NN   (NB*NPG)

// ---------------- scratch (static device globals; no runtime allocation) ----
__device__ float g_m[(size_t)NN*RK];      // aggregated input to GEMM (tf32)
__device__ float g_h[(size_t)NN*RK];      // GEMM output (pre-bias, pre-LN)
__device__ float g_mc[(size_t)NB*RK];     // compact layer-3 GEMM input (node 0)
__device__ float g_hc[(size_t)NB*RK];     // compact layer-3 GEMM output
__device__ float g_Wt[3*RK*RK];           // tf32-rounded weights [K,N] row-major
__device__ int   g_src64;
__device__ int   g_feat64;

// ---------------- helpers ---------------------------------------------------
__device__ __forceinline__ float tf32r(float x){
    unsigned u; asm("cvt.rna.tf32.f32 %0, %1;" : "=r"(u) : "f"(x));
    return __uint_as_float(u);
}
__device__ __forceinline__ float wredsum(float v){
    #pragma unroll
    for (int o = 16; o; o >>= 1) v += __shfl_xor_sync(0xffffffffu, v, o);
    return v;
}
__device__ __forceinline__ void cp_async16(void* smem, const void* g){
    unsigned s = (unsigned)__cvta_generic_to_shared(smem);
    asm volatile("cp.async.cg.shared.global [%0], [%1], 16;\n" :: "r"(s), "l"(g));
}
__device__ __forceinline__ void cp_commit(){ asm volatile("cp.async.commit_group;\n"); }
template<int W> __device__ __forceinline__ void cp_wait(){
    asm volatile("cp.async.wait_group %0;\n" :: "n"(W));
}
__device__ __forceinline__ void mma_tf32(float* c, const unsigned* a, const unsigned* b){
    asm volatile(
        "mma.sync.aligned.m16n8k8.row.col.f32.tf32.tf32.f32 "
        "{%0,%1,%2,%3},{%4,%5,%6,%7},{%8,%9},{%0,%1,%2,%3};\n"
        : "+f"(c[0]), "+f"(c[1]), "+f"(c[2]), "+f"(c[3])
        : "r"(a[0]), "r"(a[1]), "r"(a[2]), "r"(a[3]), "r"(b[0]), "r"(b[1]));
}
__device__ __forceinline__ int read_idx(const void* p, int is64, long long i){
    return is64 ? (int)((const long long*)p)[i] : ((const int*)p)[i];
}

// ---------------- dtype detection (int32 vs int64 indices) -------------------
__global__ void detect_kernel(const int* sw, const int* fw){
    const int t = threadIdx.x;
    unsigned s = __ballot_sync(0xffffffffu, sw[2*t+1] != 0);
    unsigned f = __ballot_sync(0xffffffffu, fw[2*t+1] != 0);
    if (t == 0){ g_src64 = (s == 0); g_feat64 = (f == 0); }
}

// ---------------- pre-round W to tf32 ---------------------------------------
__global__ void round_w_kernel(const float* __restrict__ Ws){
    int idx = blockIdx.x*blockDim.x + threadIdx.x;
    g_Wt[idx] = tf32r(Ws[idx]);
}

// ---------------- layer-0 aggregation: emb gather + norm + scatter-add ------
__global__ __launch_bounds__(256) void agg0_kernel(
    const void* __restrict__ featp, const void* __restrict__ srcp,
    const void* __restrict__ dstp, const float* __restrict__ emb)
{
    __shared__ float hs[NPG][RK];
    __shared__ float ms[NPG][RK];
    __shared__ int sl[EPG], dl[EPG], odeg[NPG], ideg[NPG], feats[NPG];
    __shared__ float onrm[NPG], inrm[NPG];
    const int g = blockIdx.x, tid = threadIdx.x;
    const int f64 = g_feat64, s64 = g_src64;

    if (tid < NPG){
        odeg[tid] = 0; ideg[tid] = 0;
        feats[tid] = read_idx(featp, f64, (long long)g*NPG + tid);
    }
    __syncthreads();
    if (tid < EPG){
        long long e = (long long)g*EPG + tid;
        int s = read_idx(srcp, s64, e) - g*NPG;
        int d = read_idx(dstp, s64, e) - g*NPG;
        sl[tid] = s; dl[tid] = d;
        atomicAdd(&odeg[s], 1); atomicAdd(&ideg[d], 1);
    }
    for (int idx = tid; idx < NPG*(RK/4); idx += 256){
        int i = idx/(RK/4), c4 = idx%(RK/4);
        float4 v = ((const float4*)(emb + (size_t)feats[i]*RK))[c4];
        ((float4*)&hs[i][0])[c4] = v;
        ((float4*)&ms[i][0])[c4] = make_float4(0.f,0.f,0.f,0.f);
    }
    __syncthreads();
    if (tid < NPG){
        onrm[tid] = odeg[tid] ? rsqrtf((float)odeg[tid]) : 1.0f;
        inrm[tid] = ideg[tid] ? rsqrtf((float)ideg[tid]) : 1.0f;
    }
    __syncthreads();
    const int f0 = tid, f1 = tid + 256;
    #pragma unroll
    for (int e = 0; e < EPG; e++){
        int s = sl[e], d = dl[e];
        float w = onrm[s];
        ms[d][f0] += hs[s][f0]*w;
        ms[d][f1] += hs[s][f1]*w;
    }
    __syncthreads();
    float* Mg = g_m + (size_t)g*NPG*RK;
    for (int idx = tid; idx < NPG*(RK/4); idx += 256){
        int i = idx/(RK/4), c4 = idx%(RK/4);
        float w = inrm[i];
        float4 v = ((float4*)&ms[i][0])[c4];
        v.x = tf32r(v.x*w); v.y = tf32r(v.y*w); v.z = tf32r(v.z*w); v.w = tf32r(v.w*w);
        ((float4*)Mg)[idx] = v;
    }
}

// -------- fused bias + LN + ReLU (prev layer) + aggregation (this layer) ----
// compact != 0: write ONLY node 0's aggregated row to mout + g*RK
// compact == 0: write all NPG rows to mout + g*NPG*RK
__global__ __launch_bounds__(256) void aggln_kernel(
    const void* __restrict__ srcp, const void* __restrict__ dstp,
    const float* __restrict__ bias, const float* __restrict__ gamma,
    const float* __restrict__ beta, float* __restrict__ mout, int compact)
{
    __shared__ float hs[NPG][RK];
    __shared__ float ms[NPG][RK];
    __shared__ float gsm[RK], btsm[RK];
    __shared__ int sl[EPG], dl[EPG], odeg[NPG], ideg[NPG];
    __shared__ float onrm[NPG], inrm[NPG], mu9[NPG], rs9[NPG];
    const int g = blockIdx.x, tid = threadIdx.x;
    const int s64 = g_src64;

    if (tid < NPG){ odeg[tid] = 0; ideg[tid] = 0; }
    for (int f = tid; f < RK; f += 256){ gsm[f] = gamma[f]; btsm[f] = beta[f]; }
    __syncthreads();
    if (tid < EPG){
        long long e = (long long)g*EPG + tid;
        int s = read_idx(srcp, s64, e) - g*NPG;
        int d = read_idx(dstp, s64, e) - g*NPG;
        sl[tid] = s; dl[tid] = d;
        atomicAdd(&odeg[s], 1); atomicAdd(&ideg[d], 1);
    }
    const float* Hg = g_h + (size_t)g*NPG*RK;
    for (int idx = tid; idx < NPG*(RK/4); idx += 256){
        int i = idx/(RK/4), c4 = idx%(RK/4);
        float4 v = ((const float4*)Hg)[idx];
        float4 b = ((const float4*)bias)[c4];
        v.x += b.x; v.y += b.y; v.z += b.z; v.w += b.w;
        ((float4*)&hs[i][0])[c4] = v;
    }
    __syncthreads();
    if (tid < NPG){
        onrm[tid] = odeg[tid] ? rsqrtf((float)odeg[tid]) : 1.0f;
        inrm[tid] = ideg[tid] ? rsqrtf((float)ideg[tid]) : 1.0f;
    }
    const int w = tid >> 5, ln = tid & 31;
    for (int r = w; r < NPG; r += 8){
        float s = 0.f, ss = 0.f;
        #pragma unroll
        for (int j = 0; j < RK/32; j++){ float v = hs[r][ln + j*32]; s += v; ss += v*v; }
        s = wredsum(s); ss = wredsum(ss);
        if (ln == 0){
            float mu = s*(1.0f/RK);
            mu9[r] = mu;
            rs9[r] = rsqrtf(ss*(1.0f/RK) - mu*mu + 1e-5f);
        }
    }
    __syncthreads();
    for (int idx = tid; idx < NPG*RK; idx += 256){
        int i = idx >> 9, f = idx & (RK-1);
        float v = (hs[i][f] - mu9[i])*rs9[i]*gsm[f] + btsm[f];
        hs[i][f] = fmaxf(v, 0.f)*onrm[i];
        ms[i][f] = 0.f;
    }
    __syncthreads();
    const int f0 = tid, f1 = tid + 256;
    #pragma unroll
    for (int e = 0; e < EPG; e++){
        int s = sl[e], d = dl[e];
        ms[d][f0] += hs[s][f0];
        ms[d][f1] += hs[s][f1];
    }
    __syncthreads();
    if (compact){
        float* Mg = mout + (size_t)g*RK;
        float wn = inrm[0];
        for (int c4 = tid; c4 < RK/4; c4 += 256){
            float4 v = ((float4*)&ms[0][0])[c4];
            v.x = tf32r(v.x*wn); v.y = tf32r(v.y*wn);
            v.z = tf32r(v.z*wn); v.w = tf32r(v.w*wn);
            ((float4*)Mg)[c4] = v;
        }
    } else {
        float* Mg = mout + (size_t)g*NPG*RK;
        for (int idx = tid; idx < NPG*(RK/4); idx += 256){
            int i = idx/(RK/4), c4 = idx%(RK/4);
            float wn = inrm[i];
            float4 v = ((float4*)&ms[i][0])[c4];
            v.x = tf32r(v.x*wn); v.y = tf32r(v.y*wn);
            v.z = tf32r(v.z*wn); v.w = tf32r(v.w*wn);
            ((float4*)Mg)[idx] = v;
        }
    }
}

// ------------- TF32 GEMM (mma.sync): C = A @ W   A:[M,512] W:[512,512] ------
// 128x128x32 tiles, 3-stage cp.async pipeline, ONE __syncthreads per K-tile.
#define BM 128
#define BN 128
#define BK 32
#define AS_LD (BK+8)
#define BS_LD (BN+8)
#define STAGES 3
#define STG_F (BM*AS_LD + BK*BS_LD)          // floats per stage (9472)
#define SMEM_GEMM (STAGES*STG_F*4)           // 113664 B

__global__ __launch_bounds__(256,2) void gemm_tf32_kernel(
    const float* __restrict__ A, const float* __restrict__ W,
    float* __restrict__ C)
{
    extern __shared__ float smbuf[];
    const int tid = threadIdx.x;
    const int bn = blockIdx.x, bm = blockIdx.y;
    const int lane = tid & 31, warp = tid >> 5;
    const int wm = warp & 1, wn = warp >> 1;      // 2 x 4 warp grid
    const int gid = lane >> 2, tig = lane & 3;

    float c[4][4][4];
    #pragma unroll
    for (int mt = 0; mt < 4; mt++)
        #pragma unroll
        for (int nf = 0; nf < 4; nf++)
            #pragma unroll
            for (int q = 0; q < 4; q++) c[mt][nf][q] = 0.f;

    const float* Ag = A + (size_t)bm*BM*RK;
    const float* Bg = W + bn*BN;

    auto fill = [&](int t){
        float* As = smbuf + (t % STAGES)*STG_F;
        float* Bs = As + BM*AS_LD;
        const int k0 = t*BK;
        #pragma unroll
        for (int i = 0; i < 4; i++){
            int idx = tid + i*256; int r = idx >> 3, cc = idx & 7;
            cp_async16(&As[r*AS_LD + cc*4], Ag + (size_t)r*RK + k0 + cc*4);
        }
        #pragma unroll
        for (int i = 0; i < 4; i++){
            int idx = tid + i*256; int r = idx >> 5, cc = idx & 31;
            cp_async16(&Bs[r*BS_LD + cc*4], Bg + (size_t)(k0 + r)*RK + cc*4);
        }
        cp_commit();
    };

    fill(0); fill(1);

    #pragma unroll 1
    for (int kt = 0; kt < RK/BK; kt++){
        cp_wait<1>();          // K-tile kt resident
        __syncthreads();       // + every warp done reading stage kt-1
        if (kt + 2 < RK/BK) fill(kt + 2);   // overwrites stage (kt-1)%3 : safe
        else cp_commit();                   // keep group counts aligned

        const float* Ac = smbuf + (kt % STAGES)*STG_F;
        const float* Bc = Ac + BM*AS_LD;
        #pragma unroll
        for (int ks = 0; ks < BK/8; ks++){
            const int kk = ks*8;
            unsigned a[4][4], b[4][2];
            #pragma unroll
            for (int mt = 0; mt < 4; mt++){
                int r = wm*64 + mt*16 + gid;
                a[mt][0] = __float_as_uint(Ac[ r   *AS_LD + kk + tig    ]);
                a[mt][1] = __float_as_uint(Ac[(r+8)*AS_LD + kk + tig    ]);
                a[mt][2] = __float_as_uint(Ac[ r   *AS_LD + kk + tig + 4]);
                a[mt][3] = __float_as_uint(Ac[(r+8)*AS_LD + kk + tig + 4]);
            }
            #pragma unroll
            for (int nf = 0; nf < 4; nf++){
                int cn = wn*32 + nf*8 + gid;
                b[nf][0] = __float_as_uint(Bc[(kk + tig    )*BS_LD + cn]);
                b[nf][1] = __float_as_uint(Bc[(kk + tig + 4)*BS_LD + cn]);
            }
            #pragma unroll
            for (int mt = 0; mt < 4; mt++)
                #pragma unroll
                for (int nf = 0; nf < 4; nf++)
                    mma_tf32(c[mt][nf], a[mt], b[nf]);
        }
    }
    #pragma unroll
    for (int mt = 0; mt < 4; mt++){
        int r = bm*BM + wm*64 + mt*16 + gid;
        #pragma unroll
        for (int nf = 0; nf < 4; nf++){
            int cn = bn*BN + wn*32 + nf*8 + tig*2;
            *(float2*)&C[(size_t)r*RK + cn]     = make_float2(c[mt][nf][0], c[mt][nf][1]);
            *(float2*)&C[(size_t)(r+8)*RK + cn] = make_float2(c[mt][nf][2], c[mt][nf][3]);
        }
    }
}

// ---------------- output head: bias + LN + ReLU on compact rows, dot w_out --
__global__ __launch_bounds__(256) void out_kernel(
    const float* __restrict__ bias, const float* __restrict__ gamma,
    const float* __restrict__ beta, const float* __restrict__ wout,
    const float* __restrict__ bout, float* __restrict__ out)
{
    const int g = blockIdx.x*8 + (threadIdx.x >> 5);
    const int ln = threadIdx.x & 31;
    const float* row = g_hc + (size_t)g*RK;
    float v[16]; float s = 0.f, ss = 0.f;
    #pragma unroll
    for (int j = 0; j < 16; j++){
        int f = ln + j*32;
        float x = row[f] + bias[f];
        v[j] = x; s += x; ss += x*x;
    }
    s = wredsum(s); ss = wredsum(ss);
    float mu = s*(1.0f/RK);
    float rs = rsqrtf(ss*(1.0f/RK) - mu*mu + 1e-5f);
    float dot = 0.f;
    #pragma unroll
    for (int j = 0; j < 16; j++){
        int f = ln + j*32;
        float y = fmaxf((v[j]-mu)*rs*gamma[f] + beta[f], 0.f);
        dot += y*wout[f];
    }
    dot = wredsum(dot);
    if (ln == 0) out[g] = dot + bout[0];
}

// ---------------- launcher ---------------------------------------------------
extern "C" void kernel_launch(void* const* d_in, const int* in_sizes, int n_in,
                              void* d_out, int out_size){
    (void)in_sizes; (void)n_in; (void)out_size;
    const void*  feat = d_in[0];
    const void*  src  = d_in[1];
    const void*  dst  = d_in[2];
    const float* emb  = (const float*)d_in[3];
    const float* Ws   = (const float*)d_in[4];
    const float* bs   = (const float*)d_in[5];
    const float* gam  = (const float*)d_in[6];
    const float* bet  = (const float*)d_in[7];
    const float* wout = (const float*)d_in[8];
    const float* bout = (const float*)d_in[9];
    float* out = (float*)d_out;

    cudaFuncSetAttribute(gemm_tf32_kernel,
                         cudaFuncAttributeMaxDynamicSharedMemorySize, SMEM_GEMM);

    float* gm;  cudaGetSymbolAddress((void**)&gm,  g_m);
    float* gh;  cudaGetSymbolAddress((void**)&gh,  g_h);
    float* gmc; cudaGetSymbolAddress((void**)&gmc, g_mc);
    float* ghc; cudaGetSymbolAddress((void**)&ghc, g_hc);
    float* gwt; cudaGetSymbolAddress((void**)&gwt, g_Wt);

    detect_kernel<<<1, 32>>>((const int*)src, (const int*)feat);
    round_w_kernel<<<3*RK*RK/256, 256>>>(Ws);

    agg0_kernel<<<NB, 256>>>(feat, src, dst, emb);
    dim3 gg(RK/BN, NN/BM);
    gemm_tf32_kernel<<<gg, 256, SMEM_GEMM>>>(gm, gwt, gh);
    aggln_kernel<<<NB, 256>>>(src, dst, bs,      gam,      bet,      gm,  0);
    gemm_tf32_kernel<<<gg, 256, SMEM_GEMM>>>(gm, gwt + RK*RK, gh);
    aggln_kernel<<<NB, 256>>>(src, dst, bs + RK, gam + RK, bet + RK, gmc, 1);
    dim3 gc(RK/BN, NB/BM);
    gemm_tf32_kernel<<<gc, 256, SMEM_GEMM>>>(gmc, gwt + 2*RK*RK, ghc);
    out_kernel<<<NB/8, 256>>>(bs + 2*RK, gam + 2*RK, bet + 2*RK, wout, bout, out);
}